// round 1
// baseline (speedup 1.0000x reference)
#include <cuda_runtime.h>
#include <cuda_bf16.h>

// Problem constants
#define BB 32
#define SS 256
#define TT 64
#define EE 256
#define HH 512
#define VV 32000
#define H3 1536

// ---------------- scratch (device globals; no runtime allocs) ----------------
__device__ float g_enc_gi[SS * H3 * BB];    // [t][j][b]  enc: emb@Wih^T + bih
__device__ float g_dec_gie[TT * H3 * BB];   // [t][j][b]  dec: emb@Wih[:, :E]^T + bih
__device__ float g_eo[SS * HH * BB];        // [s][k][b]  encoder outputs (h per step)
__device__ float g_h0[HH * BB];             // zeros
__device__ float g_hdec[2][HH * BB];        // decoder h double buffer [k][b]
__device__ float g_ctx[HH * BB];            // context [k][b]
__device__ float g_scores[SS * BB];         // exp(scores) [s][b]
__device__ float g_pred[(TT * BB) * (2 * HH)]; // [t*32+b][0:512]=h, [512:1024]=ctx
__device__ unsigned g_bar_cnt;
__device__ unsigned g_bar_gen;

// ---------------- grid barrier (all blocks co-resident) ----------------
__device__ __forceinline__ void grid_sync(unsigned nb) {
    __syncthreads();
    if (threadIdx.x == 0) {
        __threadfence();
        volatile unsigned* genp = &g_bar_gen;
        unsigned gen = *genp;
        if (atomicAdd(&g_bar_cnt, 1u) == nb - 1u) {
            g_bar_cnt = 0;
            __threadfence();
            *genp = gen + 1u;
        } else {
            while (*genp == gen) { }
            __threadfence();
        }
    }
    __syncthreads();
}

__device__ __forceinline__ float sigm(float x) { return 1.0f / (1.0f + __expf(-x)); }

// ---------------- init ----------------
__global__ void init_k() {
    int idx = blockIdx.x * 1024 + threadIdx.x;
    if (idx < HH * BB) g_h0[idx] = 0.0f;
}

// ---------------- gi precompute: out[t][j][b] = bih[j] + sum_e emb[tok[b]][e]*Wih[j][e]
// which=0 -> g_enc_gi (L=256, wstride=256); which=1 -> g_dec_gie (L=64, wstride=768)
__global__ void gi_kernel(const float* __restrict__ emb, const float* __restrict__ Wih,
                          const float* __restrict__ bih, const int* __restrict__ tok,
                          int L, int wstride, int which) {
    __shared__ float xs[EE * 33];   // [e][b] padded
    int t = blockIdx.x;
    int wid = threadIdx.x >> 5, lane = threadIdx.x & 31;

    // gather 32 embedding rows
    for (int bb = 0; bb < 4; bb++) {
        int b = wid * 4 + bb;
        int tv = tok[b * L + t];
        const float* er = emb + (long)tv * EE;
        for (int e = lane; e < EE; e += 32) xs[e * 33 + b] = er[e];
    }
    __syncthreads();

    float* outg = which ? g_dec_gie : g_enc_gi;
    for (int jj = 0; jj < 48; jj++) {
        int j = blockIdx.y * 384 + jj * 8 + wid;
        const float4* wv = (const float4*)(Wih + (long)j * wstride);
        float acc = 0.0f;
        #pragma unroll 8
        for (int q = 0; q < 64; q++) {
            float4 w = wv[q];
            int e = q * 4;
            acc += w.x * xs[(e + 0) * 33 + lane] + w.y * xs[(e + 1) * 33 + lane]
                 + w.z * xs[(e + 2) * 33 + lane] + w.w * xs[(e + 3) * 33 + lane];
        }
        outg[t * (H3 * BB) + j * 32 + lane] = acc + bih[j];
    }
}

// ---------------- encoder scan (persistent, 128 blocks x 512 threads) ----------------
__global__ void __launch_bounds__(512) enc_scan(const float* __restrict__ Whh,
                                                const float* __restrict__ bhh) {
    int wid = threadIdx.x >> 5, lane = threadIdx.x & 31;
    int iLocal = wid & 3;           // 0..3
    int kq = wid >> 2;              // 0..3 (k quarter)
    int i = blockIdx.x * 4 + iLocal;
    __shared__ float ps[4][3][3][32];  // [iLocal][kq-1][gate][b]

    for (int t = 0; t < SS; t++) {
        const float* hprev = t ? (g_eo + (t - 1) * (HH * BB)) : g_h0;
        float s0 = 0, s1 = 0, s2 = 0;
        {
            const float4* w0 = (const float4*)(Whh + (long)(i) * HH + kq * 128);
            const float4* w1 = (const float4*)(Whh + (long)(HH + i) * HH + kq * 128);
            const float4* w2 = (const float4*)(Whh + (long)(2 * HH + i) * HH + kq * 128);
            const float* hp = hprev + kq * 128 * 32 + lane;
            #pragma unroll 4
            for (int q = 0; q < 32; q++) {
                float h0 = hp[q * 128 + 0];
                float h1 = hp[q * 128 + 32];
                float h2 = hp[q * 128 + 64];
                float h3 = hp[q * 128 + 96];
                float4 w;
                w = w0[q]; s0 += w.x * h0 + w.y * h1 + w.z * h2 + w.w * h3;
                w = w1[q]; s1 += w.x * h0 + w.y * h1 + w.z * h2 + w.w * h3;
                w = w2[q]; s2 += w.x * h0 + w.y * h1 + w.z * h2 + w.w * h3;
            }
        }
        if (kq > 0) {
            ps[iLocal][kq - 1][0][lane] = s0;
            ps[iLocal][kq - 1][1][lane] = s1;
            ps[iLocal][kq - 1][2][lane] = s2;
        }
        __syncthreads();
        if (wid < 4) {
            // this warp's i == blockIdx.x*4 + wid
            float rh = s0 + ps[wid][0][0][lane] + ps[wid][1][0][lane] + ps[wid][2][0][lane] + bhh[i];
            float zh = s1 + ps[wid][0][1][lane] + ps[wid][1][1][lane] + ps[wid][2][1][lane] + bhh[HH + i];
            float nh = s2 + ps[wid][0][2][lane] + ps[wid][1][2][lane] + ps[wid][2][2][lane] + bhh[2 * HH + i];
            const float* gi = g_enc_gi + t * (H3 * BB);
            float ir = gi[i * 32 + lane];
            float iz = gi[(HH + i) * 32 + lane];
            float in_ = gi[(2 * HH + i) * 32 + lane];
            float r = sigm(ir + rh);
            float z = sigm(iz + zh);
            float n = tanhf(in_ + r * nh);
            float hv = hprev[i * 32 + lane];
            g_eo[t * (HH * BB) + i * 32 + lane] = (1.0f - z) * n + z * hv;
        }
        grid_sync(gridDim.x);
    }
}

// ---------------- copy final encoder h -> decoder h[0] ----------------
__global__ void copyh() {
    int idx = blockIdx.x * 1024 + threadIdx.x;
    if (idx < HH * BB) g_hdec[0][idx] = g_eo[(SS - 1) * (HH * BB) + idx];
}

// ---------------- decoder scan (persistent, 128 blocks x 512 threads) ----------------
__global__ void __launch_bounds__(512) dec_scan(const float* __restrict__ Whh,
                                                const float* __restrict__ bhh,
                                                const float* __restrict__ Wih,
                                                const int* __restrict__ src) {
    int wid = threadIdx.x >> 5, lane = threadIdx.x & 31;
    __shared__ float psA[2][8][32];
    __shared__ float psC[4][4][32];
    __shared__ float denS[32];
    __shared__ float psD[4][3][6][32];

    for (int t = 0; t < TT; t++) {
        const float* h = g_hdec[t & 1];

        // ---- Phase A: scores[s][b] = sum_k eo[s][k][b]*h[k][b]; exp + mask ----
        {
            int s = blockIdx.x * 2 + (wid & 1);
            int kq8 = wid >> 1;  // 0..7, 64 k each
            float acc = 0.0f;
            const float* eo = g_eo + s * (HH * BB) + kq8 * 64 * 32 + lane;
            const float* hp = h + kq8 * 64 * 32 + lane;
            #pragma unroll 8
            for (int k = 0; k < 64; k++) acc += eo[k * 32] * hp[k * 32];
            psA[wid & 1][kq8][lane] = acc;
            __syncthreads();
            if (wid < 2) {
                int ss = blockIdx.x * 2 + wid;
                float sc = 0.0f;
                #pragma unroll
                for (int q = 0; q < 8; q++) sc += psA[wid][q][lane];
                int tokv = src[lane * SS + ss];
                float e = (tokv == 0) ? 0.0f : __expf(sc);
                g_scores[ss * 32 + lane] = e;
            }
        }
        grid_sync(gridDim.x);

        // ---- Phase C: ctx[k][b] = sum_s e[s][b]*eo[s][k][b] / den[b] ----
        {
            int k = blockIdx.x * 4 + (wid & 3);
            int sq = wid >> 2;  // 0..3, 64 s each
            float acc = 0.0f;
            const float* eo = g_eo + sq * 64 * (HH * BB) + k * 32 + lane;
            const float* sce = g_scores + sq * 64 * 32 + lane;
            #pragma unroll 8
            for (int s = 0; s < 64; s++) acc += sce[s * 32] * eo[s * (HH * BB)];
            psC[wid & 3][sq][lane] = acc;
            if (wid == 0) {
                float d = 0.0f;
                const float* sp = g_scores + lane;
                #pragma unroll 8
                for (int s = 0; s < SS; s++) d += sp[s * 32];
                denS[lane] = d;
            }
            __syncthreads();
            if (wid < 4) {
                int kk = blockIdx.x * 4 + wid;
                float c = (psC[wid][0][lane] + psC[wid][1][lane] + psC[wid][2][lane] + psC[wid][3][lane])
                          / denS[lane];
                g_ctx[kk * 32 + lane] = c;
                g_pred[(t * 32 + lane) * (2 * HH) + HH + kk] = c;
            }
        }
        grid_sync(gridDim.x);

        // ---- Phase D: gates + h update ----
        {
            int i = blockIdx.x * 4 + (wid & 3);
            int kq = wid >> 2;  // 0..3, 128 k each
            float a0 = 0, a1 = 0, a2 = 0, c0 = 0, c1 = 0, c2 = 0;
            {
                const float4* wh0 = (const float4*)(Whh + (long)(i) * HH + kq * 128);
                const float4* wh1 = (const float4*)(Whh + (long)(HH + i) * HH + kq * 128);
                const float4* wh2 = (const float4*)(Whh + (long)(2 * HH + i) * HH + kq * 128);
                const float4* wc0 = (const float4*)(Wih + (long)(i) * 768 + EE + kq * 128);
                const float4* wc1 = (const float4*)(Wih + (long)(HH + i) * 768 + EE + kq * 128);
                const float4* wc2 = (const float4*)(Wih + (long)(2 * HH + i) * 768 + EE + kq * 128);
                const float* hp = h + kq * 128 * 32 + lane;
                const float* cp = g_ctx + kq * 128 * 32 + lane;
                #pragma unroll 4
                for (int q = 0; q < 32; q++) {
                    float h0 = hp[q * 128 + 0], h1 = hp[q * 128 + 32];
                    float h2 = hp[q * 128 + 64], h3 = hp[q * 128 + 96];
                    float x0 = cp[q * 128 + 0], x1 = cp[q * 128 + 32];
                    float x2 = cp[q * 128 + 64], x3 = cp[q * 128 + 96];
                    float4 w;
                    w = wh0[q]; a0 += w.x * h0 + w.y * h1 + w.z * h2 + w.w * h3;
                    w = wh1[q]; a1 += w.x * h0 + w.y * h1 + w.z * h2 + w.w * h3;
                    w = wh2[q]; a2 += w.x * h0 + w.y * h1 + w.z * h2 + w.w * h3;
                    w = wc0[q]; c0 += w.x * x0 + w.y * x1 + w.z * x2 + w.w * x3;
                    w = wc1[q]; c1 += w.x * x0 + w.y * x1 + w.z * x2 + w.w * x3;
                    w = wc2[q]; c2 += w.x * x0 + w.y * x1 + w.z * x2 + w.w * x3;
                }
            }
            if (kq > 0) {
                psD[wid & 3][kq - 1][0][lane] = a0;
                psD[wid & 3][kq - 1][1][lane] = a1;
                psD[wid & 3][kq - 1][2][lane] = a2;
                psD[wid & 3][kq - 1][3][lane] = c0;
                psD[wid & 3][kq - 1][4][lane] = c1;
                psD[wid & 3][kq - 1][5][lane] = c2;
            }
            __syncthreads();
            if (wid < 4) {
                float rh = a0, zh = a1, nh = a2, rc = c0, zc = c1, nc = c2;
                #pragma unroll
                for (int kk = 0; kk < 3; kk++) {
                    rh += psD[wid][kk][0][lane];
                    zh += psD[wid][kk][1][lane];
                    nh += psD[wid][kk][2][lane];
                    rc += psD[wid][kk][3][lane];
                    zc += psD[wid][kk][4][lane];
                    nc += psD[wid][kk][5][lane];
                }
                rh += bhh[i]; zh += bhh[HH + i]; nh += bhh[2 * HH + i];
                const float* gie = g_dec_gie + t * (H3 * BB);
                float ir = gie[i * 32 + lane] + rc;
                float iz = gie[(HH + i) * 32 + lane] + zc;
                float in_ = gie[(2 * HH + i) * 32 + lane] + nc;
                float r = sigm(ir + rh);
                float z = sigm(iz + zh);
                float n = tanhf(in_ + r * nh);
                float hold = h[i * 32 + lane];
                float hn = (1.0f - z) * n + z * hold;
                g_hdec[(t + 1) & 1][i * 32 + lane] = hn;
                g_pred[(t * 32 + lane) * (2 * HH) + i] = hn;
            }
        }
        grid_sync(gridDim.x);
    }
}

// ---------------- fc GEMM: out[b][t][n] = sum_k pred[t*32+b][k]*W[n][k] + bias[n]
__global__ void __launch_bounds__(256, 2) fc_gemm(const float* __restrict__ W,
                                                  const float* __restrict__ bias,
                                                  float* __restrict__ out) {
    __shared__ float As[8][132];
    __shared__ float Bs[8][132];
    int tid = threadIdx.x;
    int tx = tid & 15, ty = tid >> 4;
    int lrow = tid >> 1, lk = (tid & 1) * 4;
    int m0 = blockIdx.y * 128, n0 = blockIdx.x * 128;
    const float* Ap = g_pred + (m0 + lrow) * 1024 + lk;
    const float* Bp = W + (long)(n0 + lrow) * 1024 + lk;
    float4 av = *(const float4*)Ap;
    float4 bv = *(const float4*)Bp;
    float acc[8][8] = {};
    for (int kt = 0; kt < 128; kt++) {
        As[lk + 0][lrow] = av.x; As[lk + 1][lrow] = av.y;
        As[lk + 2][lrow] = av.z; As[lk + 3][lrow] = av.w;
        Bs[lk + 0][lrow] = bv.x; Bs[lk + 1][lrow] = bv.y;
        Bs[lk + 2][lrow] = bv.z; Bs[lk + 3][lrow] = bv.w;
        __syncthreads();
        if (kt < 127) {
            Ap += 8; Bp += 8;
            av = *(const float4*)Ap;
            bv = *(const float4*)Bp;
        }
        #pragma unroll
        for (int k = 0; k < 8; k++) {
            float a[8], b[8];
            *(float4*)(a) = *(const float4*)&As[k][ty * 8];
            *(float4*)(a + 4) = *(const float4*)&As[k][ty * 8 + 4];
            *(float4*)(b) = *(const float4*)&Bs[k][tx * 8];
            *(float4*)(b + 4) = *(const float4*)&Bs[k][tx * 8 + 4];
            #pragma unroll
            for (int i = 0; i < 8; i++)
                #pragma unroll
                for (int j = 0; j < 8; j++) acc[i][j] += a[i] * b[j];
        }
        __syncthreads();
    }
    float bb[8];
    #pragma unroll
    for (int j = 0; j < 8; j++) bb[j] = bias[n0 + tx * 8 + j];
    #pragma unroll
    for (int i = 0; i < 8; i++) {
        int m = m0 + ty * 8 + i;
        int tt = m >> 5, b = m & 31;
        float* orow = out + b * (TT * VV) + tt * VV + n0 + tx * 8;
        float4 v0 = {acc[i][0] + bb[0], acc[i][1] + bb[1], acc[i][2] + bb[2], acc[i][3] + bb[3]};
        float4 v1 = {acc[i][4] + bb[4], acc[i][5] + bb[5], acc[i][6] + bb[6], acc[i][7] + bb[7]};
        *(float4*)orow = v0;
        *(float4*)(orow + 4) = v1;
    }
}

// ---------------- launch ----------------
extern "C" void kernel_launch(void* const* d_in, const int* in_sizes, int n_in,
                              void* d_out, int out_size) {
    const int* src = (const int*)d_in[0];
    // d_in[1] = src_lens (unused by reference)
    const int* tgt = (const int*)d_in[2];
    const float* enc_emb = (const float*)d_in[3];
    const float* enc_Wih = (const float*)d_in[4];
    const float* enc_Whh = (const float*)d_in[5];
    const float* enc_bih = (const float*)d_in[6];
    const float* enc_bhh = (const float*)d_in[7];
    const float* dec_emb = (const float*)d_in[8];
    const float* dec_Wih = (const float*)d_in[9];
    const float* dec_Whh = (const float*)d_in[10];
    const float* dec_bih = (const float*)d_in[11];
    const float* dec_bhh = (const float*)d_in[12];
    const float* fc_W = (const float*)d_in[13];
    const float* fc_b = (const float*)d_in[14];
    float* out = (float*)d_out;

    init_k<<<16, 1024>>>();
    gi_kernel<<<dim3(SS, 4), 256>>>(enc_emb, enc_Wih, enc_bih, src, SS, EE, 0);
    gi_kernel<<<dim3(TT, 4), 256>>>(dec_emb, dec_Wih, dec_bih, tgt, TT, 768, 1);
    enc_scan<<<128, 512>>>(enc_Whh, enc_bhh);
    copyh<<<16, 1024>>>();
    dec_scan<<<128, 512>>>(dec_Whh, dec_bhh, dec_Wih, src);
    fc_gemm<<<dim3(VV / 128, (TT * BB) / 128), 256>>>(fc_W, fc_b, out);
}

// round 3
// speedup vs baseline: 1.2349x; 1.2349x over previous
#include <cuda_runtime.h>
#include <cuda_bf16.h>
#include <cstdint>

// Problem constants
#define BB 32
#define SS 256
#define TT 64
#define EE 256
#define HH 512
#define VV 32000
#define H3 1536

// fc GEMM config (split bf16: K = [Ah|Ah|Al] x [Wh|Wl|Wh])
#define KTOT 3072
#define GBM 128
#define GBN 128
#define GBK 64
#define GLDA 72                 // padded row (bf16 elems)
#define GNC (KTOT / GBK)        // 48
#define GBUF_B (GBM * GLDA * 2) // bytes per A (or B) buffer = 18432
#define FC_SMEM (4 * GBUF_B)    // 73728

// ---------------- scratch ----------------
__device__ float g_enc_gi[SS * H3 * BB];
__device__ float g_dec_gie[TT * H3 * BB];
__device__ float g_eo[SS * HH * BB];
__device__ float g_h0[HH * BB];
__device__ float g_hdec[2][HH * BB];
__device__ float g_ctx[HH * BB];
__device__ float g_scores[SS * BB];
__device__ float g_pred[(TT * BB) * (2 * HH)];
__device__ __nv_bfloat16 g_Wb[(size_t)VV * KTOT];
__device__ __nv_bfloat16 g_Ab[(size_t)(TT * BB) * KTOT];
__device__ unsigned g_bar_cnt;
__device__ unsigned g_bar_gen;

// ---------------- grid barrier ----------------
__device__ __forceinline__ void grid_sync(unsigned nb) {
    __syncthreads();
    if (threadIdx.x == 0) {
        __threadfence();
        volatile unsigned* genp = &g_bar_gen;
        unsigned gen = *genp;
        if (atomicAdd(&g_bar_cnt, 1u) == nb - 1u) {
            g_bar_cnt = 0;
            __threadfence();
            *genp = gen + 1u;
        } else {
            while (*genp == gen) { }
            __threadfence();
        }
    }
    __syncthreads();
}

__device__ __forceinline__ float sigm(float x) { return 1.0f / (1.0f + __expf(-x)); }

__device__ __forceinline__ uint32_t smem_u32(const void* p) {
    uint32_t a;
    asm("{ .reg .u64 t; cvta.to.shared.u64 t, %1; cvt.u32.u64 %0, t; }" : "=r"(a) : "l"(p));
    return a;
}
__device__ __forceinline__ void cpasync16(uint32_t dst, const void* src) {
    asm volatile("cp.async.cg.shared.global [%0], [%1], 16;" :: "r"(dst), "l"(src) : "memory");
}
#define LDSM4(r0, r1, r2, r3, addr) \
    asm volatile("ldmatrix.sync.aligned.m8n8.x4.shared.b16 {%0,%1,%2,%3}, [%4];" \
                 : "=r"(r0), "=r"(r1), "=r"(r2), "=r"(r3) : "r"(addr))
#define MMA16816(c, a, b0, b1) \
    asm volatile("mma.sync.aligned.m16n8k16.row.col.f32.bf16.bf16.f32 " \
                 "{%0,%1,%2,%3}, {%4,%5,%6,%7}, {%8,%9}, {%0,%1,%2,%3};" \
                 : "+f"((c)[0]), "+f"((c)[1]), "+f"((c)[2]), "+f"((c)[3]) \
                 : "r"((a)[0]), "r"((a)[1]), "r"((a)[2]), "r"((a)[3]), "r"(b0), "r"(b1))

// ---------------- init ----------------
__global__ void init_k() {
    int idx = blockIdx.x * 1024 + threadIdx.x;
    if (idx < HH * BB) g_h0[idx] = 0.0f;
}

// ---------------- W split: g_Wb[n][0:1024)=hi, [1024:2048)=lo, [2048:3072)=hi
__global__ void convW(const float* __restrict__ W) {
    size_t i = (size_t)blockIdx.x * 1024 + threadIdx.x;
    float4 v = ((const float4*)W)[i];
    size_t n = i >> 8;
    size_t k4 = (i & 255) * 4;
    __nv_bfloat16 h0 = __float2bfloat16(v.x), h1 = __float2bfloat16(v.y);
    __nv_bfloat16 h2 = __float2bfloat16(v.z), h3 = __float2bfloat16(v.w);
    __nv_bfloat16 l0 = __float2bfloat16(v.x - __bfloat162float(h0));
    __nv_bfloat16 l1 = __float2bfloat16(v.y - __bfloat162float(h1));
    __nv_bfloat16 l2 = __float2bfloat16(v.z - __bfloat162float(h2));
    __nv_bfloat16 l3 = __float2bfloat16(v.w - __bfloat162float(h3));
    __nv_bfloat162 hA = {h0, h1}, hB = {h2, h3}, lA = {l0, l1}, lB = {l2, l3};
    __nv_bfloat16* dst = g_Wb + n * KTOT;
    *(__nv_bfloat162*)(dst + k4) = hA;          *(__nv_bfloat162*)(dst + k4 + 2) = hB;
    *(__nv_bfloat162*)(dst + 1024 + k4) = lA;   *(__nv_bfloat162*)(dst + 1024 + k4 + 2) = lB;
    *(__nv_bfloat162*)(dst + 2048 + k4) = hA;   *(__nv_bfloat162*)(dst + 2048 + k4 + 2) = hB;
}

// ---------------- pred split: g_Ab[m][0:1024)=hi, [1024:2048)=hi, [2048:3072)=lo
__global__ void convA() {
    size_t i = (size_t)blockIdx.x * 1024 + threadIdx.x;
    float4 v = ((const float4*)g_pred)[i];
    size_t m = i >> 8;
    size_t k4 = (i & 255) * 4;
    __nv_bfloat16 h0 = __float2bfloat16(v.x), h1 = __float2bfloat16(v.y);
    __nv_bfloat16 h2 = __float2bfloat16(v.z), h3 = __float2bfloat16(v.w);
    __nv_bfloat16 l0 = __float2bfloat16(v.x - __bfloat162float(h0));
    __nv_bfloat16 l1 = __float2bfloat16(v.y - __bfloat162float(h1));
    __nv_bfloat16 l2 = __float2bfloat16(v.z - __bfloat162float(h2));
    __nv_bfloat16 l3 = __float2bfloat16(v.w - __bfloat162float(h3));
    __nv_bfloat162 hA = {h0, h1}, hB = {h2, h3}, lA = {l0, l1}, lB = {l2, l3};
    __nv_bfloat16* dst = g_Ab + m * KTOT;
    *(__nv_bfloat162*)(dst + k4) = hA;          *(__nv_bfloat162*)(dst + k4 + 2) = hB;
    *(__nv_bfloat162*)(dst + 1024 + k4) = hA;   *(__nv_bfloat162*)(dst + 1024 + k4 + 2) = hB;
    *(__nv_bfloat162*)(dst + 2048 + k4) = lA;   *(__nv_bfloat162*)(dst + 2048 + k4 + 2) = lB;
}

// ---------------- gi precompute ----------------
__global__ void gi_kernel(const float* __restrict__ emb, const float* __restrict__ Wih,
                          const float* __restrict__ bih, const int* __restrict__ tok,
                          int L, int wstride, int which) {
    __shared__ float xs[EE * 33];
    int t = blockIdx.x;
    int wid = threadIdx.x >> 5, lane = threadIdx.x & 31;
    for (int bb = 0; bb < 4; bb++) {
        int b = wid * 4 + bb;
        int tv = tok[b * L + t];
        const float* er = emb + (long)tv * EE;
        for (int e = lane; e < EE; e += 32) xs[e * 33 + b] = er[e];
    }
    __syncthreads();
    float* outg = which ? g_dec_gie : g_enc_gi;
    for (int jj = 0; jj < 48; jj++) {
        int j = blockIdx.y * 384 + jj * 8 + wid;
        const float4* wv = (const float4*)(Wih + (long)j * wstride);
        float acc = 0.0f;
        #pragma unroll 8
        for (int q = 0; q < 64; q++) {
            float4 w = wv[q];
            int e = q * 4;
            acc += w.x * xs[(e + 0) * 33 + lane] + w.y * xs[(e + 1) * 33 + lane]
                 + w.z * xs[(e + 2) * 33 + lane] + w.w * xs[(e + 3) * 33 + lane];
        }
        outg[t * (H3 * BB) + j * 32 + lane] = acc + bih[j];
    }
}

// ---------------- encoder scan ----------------
__global__ void __launch_bounds__(512) enc_scan(const float* __restrict__ Whh,
                                                const float* __restrict__ bhh) {
    int wid = threadIdx.x >> 5, lane = threadIdx.x & 31;
    int iLocal = wid & 3;
    int kq = wid >> 2;
    int i = blockIdx.x * 4 + iLocal;
    __shared__ float ps[4][3][3][32];

    for (int t = 0; t < SS; t++) {
        const float* hprev = t ? (g_eo + (t - 1) * (HH * BB)) : g_h0;
        float s0 = 0, s1 = 0, s2 = 0;
        {
            const float4* w0 = (const float4*)(Whh + (long)(i) * HH + kq * 128);
            const float4* w1 = (const float4*)(Whh + (long)(HH + i) * HH + kq * 128);
            const float4* w2 = (const float4*)(Whh + (long)(2 * HH + i) * HH + kq * 128);
            const float* hp = hprev + kq * 128 * 32 + lane;
            #pragma unroll 4
            for (int q = 0; q < 32; q++) {
                float h0 = hp[q * 128 + 0];
                float h1 = hp[q * 128 + 32];
                float h2 = hp[q * 128 + 64];
                float h3 = hp[q * 128 + 96];
                float4 w;
                w = w0[q]; s0 += w.x * h0 + w.y * h1 + w.z * h2 + w.w * h3;
                w = w1[q]; s1 += w.x * h0 + w.y * h1 + w.z * h2 + w.w * h3;
                w = w2[q]; s2 += w.x * h0 + w.y * h1 + w.z * h2 + w.w * h3;
            }
        }
        if (kq > 0) {
            ps[iLocal][kq - 1][0][lane] = s0;
            ps[iLocal][kq - 1][1][lane] = s1;
            ps[iLocal][kq - 1][2][lane] = s2;
        }
        __syncthreads();
        if (wid < 4) {
            float rh = s0 + ps[wid][0][0][lane] + ps[wid][1][0][lane] + ps[wid][2][0][lane] + bhh[i];
            float zh = s1 + ps[wid][0][1][lane] + ps[wid][1][1][lane] + ps[wid][2][1][lane] + bhh[HH + i];
            float nh = s2 + ps[wid][0][2][lane] + ps[wid][1][2][lane] + ps[wid][2][2][lane] + bhh[2 * HH + i];
            const float* gi = g_enc_gi + t * (H3 * BB);
            float ir = gi[i * 32 + lane];
            float iz = gi[(HH + i) * 32 + lane];
            float in_ = gi[(2 * HH + i) * 32 + lane];
            float r = sigm(ir + rh);
            float z = sigm(iz + zh);
            float n = tanhf(in_ + r * nh);
            float hv = hprev[i * 32 + lane];
            g_eo[t * (HH * BB) + i * 32 + lane] = (1.0f - z) * n + z * hv;
        }
        grid_sync(gridDim.x);
    }
}

__global__ void copyh() {
    int idx = blockIdx.x * 1024 + threadIdx.x;
    if (idx < HH * BB) g_hdec[0][idx] = g_eo[(SS - 1) * (HH * BB) + idx];
}

// ---------------- decoder scan ----------------
__global__ void __launch_bounds__(512) dec_scan(const float* __restrict__ Whh,
                                                const float* __restrict__ bhh,
                                                const float* __restrict__ Wih,
                                                const int* __restrict__ src) {
    int wid = threadIdx.x >> 5, lane = threadIdx.x & 31;
    __shared__ float psA[2][8][32];
    __shared__ float psC[4][4][32];
    __shared__ float denS[32];
    __shared__ float psD[4][3][6][32];

    for (int t = 0; t < TT; t++) {
        const float* h = g_hdec[t & 1];
        {
            int s = blockIdx.x * 2 + (wid & 1);
            int kq8 = wid >> 1;
            float acc = 0.0f;
            const float* eo = g_eo + s * (HH * BB) + kq8 * 64 * 32 + lane;
            const float* hp = h + kq8 * 64 * 32 + lane;
            #pragma unroll 8
            for (int k = 0; k < 64; k++) acc += eo[k * 32] * hp[k * 32];
            psA[wid & 1][kq8][lane] = acc;
            __syncthreads();
            if (wid < 2) {
                int ss2 = blockIdx.x * 2 + wid;
                float sc = 0.0f;
                #pragma unroll
                for (int q = 0; q < 8; q++) sc += psA[wid][q][lane];
                int tokv = src[lane * SS + ss2];
                float e = (tokv == 0) ? 0.0f : __expf(sc);
                g_scores[ss2 * 32 + lane] = e;
            }
        }
        grid_sync(gridDim.x);
        {
            int k = blockIdx.x * 4 + (wid & 3);
            int sq = wid >> 2;
            float acc = 0.0f;
            const float* eo = g_eo + sq * 64 * (HH * BB) + k * 32 + lane;
            const float* sce = g_scores + sq * 64 * 32 + lane;
            #pragma unroll 8
            for (int s = 0; s < 64; s++) acc += sce[s * 32] * eo[s * (HH * BB)];
            psC[wid & 3][sq][lane] = acc;
            if (wid == 0) {
                float d = 0.0f;
                const float* sp = g_scores + lane;
                #pragma unroll 8
                for (int s = 0; s < SS; s++) d += sp[s * 32];
                denS[lane] = d;
            }
            __syncthreads();
            if (wid < 4) {
                int kk = blockIdx.x * 4 + wid;
                float c = (psC[wid][0][lane] + psC[wid][1][lane] + psC[wid][2][lane] + psC[wid][3][lane])
                          / denS[lane];
                g_ctx[kk * 32 + lane] = c;
                g_pred[(t * 32 + lane) * (2 * HH) + HH + kk] = c;
            }
        }
        grid_sync(gridDim.x);
        {
            int i = blockIdx.x * 4 + (wid & 3);
            int kq = wid >> 2;
            float a0 = 0, a1 = 0, a2 = 0, c0 = 0, c1 = 0, c2 = 0;
            {
                const float4* wh0 = (const float4*)(Whh + (long)(i) * HH + kq * 128);
                const float4* wh1 = (const float4*)(Whh + (long)(HH + i) * HH + kq * 128);
                const float4* wh2 = (const float4*)(Whh + (long)(2 * HH + i) * HH + kq * 128);
                const float4* wc0 = (const float4*)(Wih + (long)(i) * 768 + EE + kq * 128);
                const float4* wc1 = (const float4*)(Wih + (long)(HH + i) * 768 + EE + kq * 128);
                const float4* wc2 = (const float4*)(Wih + (long)(2 * HH + i) * 768 + EE + kq * 128);
                const float* hp = h + kq * 128 * 32 + lane;
                const float* cp = g_ctx + kq * 128 * 32 + lane;
                #pragma unroll 4
                for (int q = 0; q < 32; q++) {
                    float h0 = hp[q * 128 + 0], h1 = hp[q * 128 + 32];
                    float h2 = hp[q * 128 + 64], h3 = hp[q * 128 + 96];
                    float x0 = cp[q * 128 + 0], x1 = cp[q * 128 + 32];
                    float x2 = cp[q * 128 + 64], x3 = cp[q * 128 + 96];
                    float4 w;
                    w = wh0[q]; a0 += w.x * h0 + w.y * h1 + w.z * h2 + w.w * h3;
                    w = wh1[q]; a1 += w.x * h0 + w.y * h1 + w.z * h2 + w.w * h3;
                    w = wh2[q]; a2 += w.x * h0 + w.y * h1 + w.z * h2 + w.w * h3;
                    w = wc0[q]; c0 += w.x * x0 + w.y * x1 + w.z * x2 + w.w * x3;
                    w = wc1[q]; c1 += w.x * x0 + w.y * x1 + w.z * x2 + w.w * x3;
                    w = wc2[q]; c2 += w.x * x0 + w.y * x1 + w.z * x2 + w.w * x3;
                }
            }
            if (kq > 0) {
                psD[wid & 3][kq - 1][0][lane] = a0;
                psD[wid & 3][kq - 1][1][lane] = a1;
                psD[wid & 3][kq - 1][2][lane] = a2;
                psD[wid & 3][kq - 1][3][lane] = c0;
                psD[wid & 3][kq - 1][4][lane] = c1;
                psD[wid & 3][kq - 1][5][lane] = c2;
            }
            __syncthreads();
            if (wid < 4) {
                float rh = a0, zh = a1, nh = a2, rc = c0, zc = c1, nc = c2;
                #pragma unroll
                for (int kk = 0; kk < 3; kk++) {
                    rh += psD[wid][kk][0][lane];
                    zh += psD[wid][kk][1][lane];
                    nh += psD[wid][kk][2][lane];
                    rc += psD[wid][kk][3][lane];
                    zc += psD[wid][kk][4][lane];
                    nc += psD[wid][kk][5][lane];
                }
                rh += bhh[i]; zh += bhh[HH + i]; nh += bhh[2 * HH + i];
                const float* gie = g_dec_gie + t * (H3 * BB);
                float ir = gie[i * 32 + lane] + rc;
                float iz = gie[(HH + i) * 32 + lane] + zc;
                float in_ = gie[(2 * HH + i) * 32 + lane] + nc;
                float r = sigm(ir + rh);
                float z = sigm(iz + zh);
                float n = tanhf(in_ + r * nh);
                float hold = h[i * 32 + lane];
                float hn = (1.0f - z) * n + z * hold;
                g_hdec[(t + 1) & 1][i * 32 + lane] = hn;
                g_pred[(t * 32 + lane) * (2 * HH) + i] = hn;
            }
        }
        grid_sync(gridDim.x);
    }
}

// ---------------- fc GEMM via mma.sync (HMMA bf16, K=3072) ----------------
// grid (16 m-blocks fast, 250 n-blocks), 256 thr = 8 warps (4m x 2n), warp 32x64.
__global__ void __launch_bounds__(256) fc_mma(const float* __restrict__ bias,
                                              float* __restrict__ out) {
    extern __shared__ uint8_t dynsmem[];
    uint32_t sA = smem_u32(dynsmem);                 // A: 2 bufs x 128 x 72 bf16
    uint32_t sB = sA + 2 * GBUF_B;                   // B: same

    int tid = threadIdx.x;
    int wid = tid >> 5, lane = tid & 31;
    int wm = wid & 3, wn = wid >> 2;
    int m0 = blockIdx.x * GBM;
    int n0 = blockIdx.y * GBN;

    const char* Ag = (const char*)(g_Ab + (size_t)m0 * KTOT);
    const char* Bg = (const char*)(g_Wb + (size_t)n0 * KTOT);

    // per-thread load slots: 4 x 16B each for A and B per chunk
    int lrow = tid >> 3;          // 0..31 base row group (x4)
    int lu = tid & 7;             // 16B unit in row
    // chunk loader
    auto load_chunk = [&](int kc, int s) {
        uint32_t sa = sA + s * GBUF_B;
        uint32_t sbm = sB + s * GBUF_B;
        size_t gk = (size_t)kc * GBK * 2;   // byte offset in k
        #pragma unroll
        for (int it = 0; it < 4; it++) {
            int row = it * 32 + lrow;
            uint32_t doff = (uint32_t)(row * (GLDA * 2) + lu * 16);
            cpasync16(sa + doff, Ag + (size_t)row * (KTOT * 2) + gk + lu * 16);
            cpasync16(sbm + doff, Bg + (size_t)row * (KTOT * 2) + gk + lu * 16);
        }
        asm volatile("cp.async.commit_group;" ::: "memory");
    };

    float acc[2][8][4];
    #pragma unroll
    for (int a = 0; a < 2; a++)
        #pragma unroll
        for (int b = 0; b < 8; b++)
            #pragma unroll
            for (int c = 0; c < 4; c++) acc[a][b][c] = 0.0f;

    // ldmatrix base addresses (bytes)
    uint32_t aBase = (uint32_t)(((wm * 32 + (lane & 15)) * GLDA + (lane >> 4) * 8) * 2);
    uint32_t bBase = (uint32_t)(((wn * 64 + (lane & 7) + ((lane >> 4) & 1) * 8) * GLDA
                                 + ((lane >> 3) & 1) * 8) * 2);

    load_chunk(0, 0);

    for (int kc = 0; kc < GNC; kc++) {
        int s = kc & 1;
        if (kc + 1 < GNC) {
            load_chunk(kc + 1, s ^ 1);
            asm volatile("cp.async.wait_group 1;" ::: "memory");
        } else {
            asm volatile("cp.async.wait_group 0;" ::: "memory");
        }
        __syncthreads();

        uint32_t sa = sA + s * GBUF_B + aBase;
        uint32_t sbm = sB + s * GBUF_B + bBase;
        #pragma unroll
        for (int ks = 0; ks < 4; ks++) {
            uint32_t koff = (uint32_t)(ks * 16 * 2);
            uint32_t a0[4], a1[4];
            LDSM4(a0[0], a0[1], a0[2], a0[3], sa + koff);
            LDSM4(a1[0], a1[1], a1[2], a1[3], sa + 16 * GLDA * 2 + koff);
            uint32_t bf[16];
            #pragma unroll
            for (int nt = 0; nt < 4; nt++)
                LDSM4(bf[nt * 4 + 0], bf[nt * 4 + 1], bf[nt * 4 + 2], bf[nt * 4 + 3],
                      sbm + nt * 16 * GLDA * 2 + koff);
            #pragma unroll
            for (int j = 0; j < 8; j++) {
                int nt = j >> 1, hf = j & 1;
                MMA16816(acc[0][j], a0, bf[nt * 4 + hf * 2], bf[nt * 4 + hf * 2 + 1]);
                MMA16816(acc[1][j], a1, bf[nt * 4 + hf * 2], bf[nt * 4 + hf * 2 + 1]);
            }
        }
        __syncthreads();
    }

    // epilogue
    float bv[8][2];
    #pragma unroll
    for (int j = 0; j < 8; j++) {
        int n = n0 + wn * 64 + j * 8 + (lane & 3) * 2;
        bv[j][0] = __ldg(bias + n);
        bv[j][1] = __ldg(bias + n + 1);
    }
    #pragma unroll
    for (int mt = 0; mt < 2; mt++) {
        #pragma unroll
        for (int half = 0; half < 2; half++) {
            int m = m0 + wm * 32 + mt * 16 + (lane >> 2) + half * 8;
            int t = m >> 5, b = m & 31;
            float* orow = out + (size_t)b * (TT * VV) + (size_t)t * VV;
            #pragma unroll
            for (int j = 0; j < 8; j++) {
                int n = n0 + wn * 64 + j * 8 + (lane & 3) * 2;
                float2 v;
                v.x = acc[mt][j][half * 2 + 0] + bv[j][0];
                v.y = acc[mt][j][half * 2 + 1] + bv[j][1];
                *(float2*)(orow + n) = v;
            }
        }
    }
}

// ---------------- launch ----------------
extern "C" void kernel_launch(void* const* d_in, const int* in_sizes, int n_in,
                              void* d_out, int out_size) {
    const int* src = (const int*)d_in[0];
    const int* tgt = (const int*)d_in[2];
    const float* enc_emb = (const float*)d_in[3];
    const float* enc_Wih = (const float*)d_in[4];
    const float* enc_Whh = (const float*)d_in[5];
    const float* enc_bih = (const float*)d_in[6];
    const float* enc_bhh = (const float*)d_in[7];
    const float* dec_emb = (const float*)d_in[8];
    const float* dec_Wih = (const float*)d_in[9];
    const float* dec_Whh = (const float*)d_in[10];
    const float* dec_bih = (const float*)d_in[11];
    const float* dec_bhh = (const float*)d_in[12];
    const float* fc_W = (const float*)d_in[13];
    const float* fc_b = (const float*)d_in[14];
    float* out = (float*)d_out;

    cudaFuncSetAttribute(fc_mma, cudaFuncAttributeMaxDynamicSharedMemorySize, FC_SMEM);

    init_k<<<16, 1024>>>();
    convW<<<(VV * 1024) / 4096, 1024>>>(fc_W);
    gi_kernel<<<dim3(SS, 4), 256>>>(enc_emb, enc_Wih, enc_bih, src, SS, EE, 0);
    gi_kernel<<<dim3(TT, 4), 256>>>(dec_emb, dec_Wih, dec_bih, tgt, TT, 768, 1);
    enc_scan<<<128, 512>>>(enc_Whh, enc_bhh);
    copyh<<<16, 1024>>>();
    dec_scan<<<128, 512>>>(dec_Whh, dec_bhh, dec_Wih, src);
    convA<<<512, 1024>>>();
    fc_mma<<<dim3(TT * BB / GBM, VV / GBN), 256, FC_SMEM>>>(fc_b, out);
}

// round 6
// speedup vs baseline: 1.4128x; 1.1440x over previous
#include <cuda_runtime.h>
#include <cuda_bf16.h>
#include <cstdint>

// Problem constants
#define BB 32
#define SS 256
#define TT 64
#define EE 256
#define HH 512
#define VV 32000
#define H3 1536

// fc GEMM config (split bf16: K = [Ah|Ah|Al] x [Wh|Wl|Wh])
#define KTOT 3072
#define GBM 128
#define GBN 128
#define GBK 64
#define GLDA 72                 // padded row (bf16 elems)
#define GNC (KTOT / GBK)        // 48
#define GBUF_B (GBM * GLDA * 2) // 18432 bytes
#define FC_SMEM (4 * GBUF_B)    // 73728

// gi GEMM config (K = 768 = [Eh|Eh|El] x [Wh|Wl|Wh])
#define GIK 768
#define GINC (GIK / GBK)        // 12

// ---------------- scratch ----------------
__device__ float g_enc_gi[SS * H3 * BB];
__device__ float g_dec_gie[TT * H3 * BB];
__device__ float g_eo[SS * HH * BB];
__device__ float g_h0[HH * BB];
__device__ float g_hdec[2][HH * BB];
__device__ float g_ctx[HH * BB];
__device__ float g_scores[SS * BB];
__device__ float g_pred[(TT * BB) * (2 * HH)];
__device__ __nv_bfloat16 g_Wb[(size_t)VV * KTOT];
__device__ __nv_bfloat16 g_Ab[(size_t)(TT * BB) * KTOT];
__device__ __nv_bfloat16 g_Xe[(size_t)(SS * BB) * GIK];   // enc emb split
__device__ __nv_bfloat16 g_Xd[(size_t)(TT * BB) * GIK];   // dec emb split
__device__ __nv_bfloat16 g_We[(size_t)H3 * GIK];          // enc Wih split
__device__ __nv_bfloat16 g_Wd[(size_t)H3 * GIK];          // dec Wih[:, :E] split
__device__ unsigned g_bar_cnt;
__device__ unsigned g_bar_gen;

// ---------------- grid barrier (proven Round-1 implementation) ----------------
__device__ __forceinline__ void grid_sync(unsigned nb) {
    __syncthreads();
    if (threadIdx.x == 0) {
        __threadfence();
        volatile unsigned* genp = &g_bar_gen;
        unsigned gen = *genp;
        if (atomicAdd(&g_bar_cnt, 1u) == nb - 1u) {
            g_bar_cnt = 0;
            __threadfence();
            *genp = gen + 1u;
        } else {
            while (*genp == gen) { }
            __threadfence();
        }
    }
    __syncthreads();
}

__device__ __forceinline__ float sigm(float x) { return 1.0f / (1.0f + __expf(-x)); }

__device__ __forceinline__ uint32_t smem_u32(const void* p) {
    uint32_t a;
    asm("{ .reg .u64 t; cvta.to.shared.u64 t, %1; cvt.u32.u64 %0, t; }" : "=r"(a) : "l"(p));
    return a;
}
__device__ __forceinline__ void cpasync16(uint32_t dst, const void* src) {
    asm volatile("cp.async.cg.shared.global [%0], [%1], 16;" :: "r"(dst), "l"(src) : "memory");
}
#define LDSM4(r0, r1, r2, r3, addr) \
    asm volatile("ldmatrix.sync.aligned.m8n8.x4.shared.b16 {%0,%1,%2,%3}, [%4];" \
                 : "=r"(r0), "=r"(r1), "=r"(r2), "=r"(r3) : "r"(addr))
#define MMA16816(c, a, b0, b1) \
    asm volatile("mma.sync.aligned.m16n8k16.row.col.f32.bf16.bf16.f32 " \
                 "{%0,%1,%2,%3}, {%4,%5,%6,%7}, {%8,%9}, {%0,%1,%2,%3};" \
                 : "+f"((c)[0]), "+f"((c)[1]), "+f"((c)[2]), "+f"((c)[3]) \
                 : "r"((a)[0]), "r"((a)[1]), "r"((a)[2]), "r"((a)[3]), "r"(b0), "r"(b1))

// ---------------- init ----------------
__global__ void init_k() {
    int idx = blockIdx.x * 1024 + threadIdx.x;
    if (idx < HH * BB) g_h0[idx] = 0.0f;
}

// split helpers
__device__ __forceinline__ void split4(float4 v, __nv_bfloat162& hA, __nv_bfloat162& hB,
                                       __nv_bfloat162& lA, __nv_bfloat162& lB) {
    __nv_bfloat16 h0 = __float2bfloat16(v.x), h1 = __float2bfloat16(v.y);
    __nv_bfloat16 h2 = __float2bfloat16(v.z), h3 = __float2bfloat16(v.w);
    __nv_bfloat16 l0 = __float2bfloat16(v.x - __bfloat162float(h0));
    __nv_bfloat16 l1 = __float2bfloat16(v.y - __bfloat162float(h1));
    __nv_bfloat16 l2 = __float2bfloat16(v.z - __bfloat162float(h2));
    __nv_bfloat16 l3 = __float2bfloat16(v.w - __bfloat162float(h3));
    hA = {h0, h1}; hB = {h2, h3}; lA = {l0, l1}; lB = {l2, l3};
}

// ---------------- W split: g_Wb[n] = [hi(1024) | lo(1024) | hi(1024)]
__global__ void convW(const float* __restrict__ W) {
    size_t i = (size_t)blockIdx.x * 1024 + threadIdx.x;
    float4 v = ((const float4*)W)[i];
    size_t n = i >> 8;
    size_t k4 = (i & 255) * 4;
    __nv_bfloat162 hA, hB, lA, lB;
    split4(v, hA, hB, lA, lB);
    __nv_bfloat16* dst = g_Wb + n * KTOT;
    *(__nv_bfloat162*)(dst + k4) = hA;          *(__nv_bfloat162*)(dst + k4 + 2) = hB;
    *(__nv_bfloat162*)(dst + 1024 + k4) = lA;   *(__nv_bfloat162*)(dst + 1024 + k4 + 2) = lB;
    *(__nv_bfloat162*)(dst + 2048 + k4) = hA;   *(__nv_bfloat162*)(dst + 2048 + k4 + 2) = hB;
}

// ---------------- pred split: g_Ab[m] = [hi | hi | lo]
__global__ void convA() {
    size_t i = (size_t)blockIdx.x * 1024 + threadIdx.x;
    float4 v = ((const float4*)g_pred)[i];
    size_t m = i >> 8;
    size_t k4 = (i & 255) * 4;
    __nv_bfloat162 hA, hB, lA, lB;
    split4(v, hA, hB, lA, lB);
    __nv_bfloat16* dst = g_Ab + m * KTOT;
    *(__nv_bfloat162*)(dst + k4) = hA;          *(__nv_bfloat162*)(dst + k4 + 2) = hB;
    *(__nv_bfloat162*)(dst + 1024 + k4) = hA;   *(__nv_bfloat162*)(dst + 1024 + k4 + 2) = hB;
    *(__nv_bfloat162*)(dst + 2048 + k4) = lA;   *(__nv_bfloat162*)(dst + 2048 + k4 + 2) = lB;
}

// ---------------- gather embedding rows + split: X[m=t*32+b] = [hi | hi | lo], K=768
// which=0 -> g_Xe, which=1 -> g_Xd   (globals referenced in DEVICE code)
__global__ void gatherX(const float* __restrict__ emb, const int* __restrict__ tok,
                        int L, int which) {
    __nv_bfloat16* X = which ? g_Xd : g_Xe;
    int m = blockIdx.x * 8 + (threadIdx.x >> 5);
    int lane = threadIdx.x & 31;
    int t = m >> 5, b = m & 31;
    int tv = tok[b * L + t];
    const float4* er = (const float4*)(emb + (size_t)tv * EE);
    __nv_bfloat16* dst = X + (size_t)m * GIK;
    #pragma unroll
    for (int q = 0; q < 2; q++) {
        float4 v = er[lane * 2 + q];
        int e = lane * 8 + q * 4;
        __nv_bfloat162 hA, hB, lA, lB;
        split4(v, hA, hB, lA, lB);
        *(__nv_bfloat162*)(dst + e) = hA;            *(__nv_bfloat162*)(dst + e + 2) = hB;
        *(__nv_bfloat162*)(dst + 256 + e) = hA;      *(__nv_bfloat162*)(dst + 256 + e + 2) = hB;
        *(__nv_bfloat162*)(dst + 512 + e) = lA;      *(__nv_bfloat162*)(dst + 512 + e + 2) = lB;
    }
}

// ---------------- split Wih rows (first 256 cols): out[j] = [hi | lo | hi], K=768
// which=0 -> g_We, which=1 -> g_Wd
__global__ void splitWih(const float* __restrict__ W, int stride, int which) {
    __nv_bfloat16* out = which ? g_Wd : g_We;
    int j = blockIdx.x * 8 + (threadIdx.x >> 5);
    int lane = threadIdx.x & 31;
    const float4* wr = (const float4*)(W + (size_t)j * stride);
    __nv_bfloat16* dst = out + (size_t)j * GIK;
    #pragma unroll
    for (int q = 0; q < 2; q++) {
        float4 v = wr[lane * 2 + q];
        int e = lane * 8 + q * 4;
        __nv_bfloat162 hA, hB, lA, lB;
        split4(v, hA, hB, lA, lB);
        *(__nv_bfloat162*)(dst + e) = hA;            *(__nv_bfloat162*)(dst + e + 2) = hB;
        *(__nv_bfloat162*)(dst + 256 + e) = lA;      *(__nv_bfloat162*)(dst + 256 + e + 2) = lB;
        *(__nv_bfloat162*)(dst + 512 + e) = hA;      *(__nv_bfloat162*)(dst + 512 + e + 2) = hB;
    }
}

// ---------------- gi GEMM via HMMA: outg[t][j][b] = X[m] . Wsp[j] + bih[j]
// which=0 -> (g_Xe, g_We, g_enc_gi), which=1 -> (g_Xd, g_Wd, g_dec_gie)
__global__ void __launch_bounds__(256) gi_mma(const float* __restrict__ bih, int which) {
    extern __shared__ uint8_t dynsmem[];
    uint32_t sA = smem_u32(dynsmem);
    uint32_t sB = sA + 2 * GBUF_B;

    const __nv_bfloat16* A = which ? g_Xd : g_Xe;
    const __nv_bfloat16* Bm = which ? g_Wd : g_We;
    float* outg = which ? g_dec_gie : g_enc_gi;

    int tid = threadIdx.x;
    int wid = tid >> 5, lane = tid & 31;
    int wm = wid & 3, wn = wid >> 2;
    int m0 = blockIdx.x * GBM;
    int n0 = blockIdx.y * GBN;

    const char* Ag = (const char*)(A + (size_t)m0 * GIK);
    const char* Bg = (const char*)(Bm + (size_t)n0 * GIK);
    int lrow = tid >> 3, lu = tid & 7;

    auto load_chunk = [&](int kc, int s) {
        uint32_t sa = sA + s * GBUF_B;
        uint32_t sbm = sB + s * GBUF_B;
        size_t gk = (size_t)kc * GBK * 2;
        #pragma unroll
        for (int it = 0; it < 4; it++) {
            int row = it * 32 + lrow;
            uint32_t doff = (uint32_t)(row * (GLDA * 2) + lu * 16);
            cpasync16(sa + doff, Ag + (size_t)row * (GIK * 2) + gk + lu * 16);
            cpasync16(sbm + doff, Bg + (size_t)row * (GIK * 2) + gk + lu * 16);
        }
        asm volatile("cp.async.commit_group;" ::: "memory");
    };

    float acc[2][8][4];
    #pragma unroll
    for (int a = 0; a < 2; a++)
        #pragma unroll
        for (int b = 0; b < 8; b++)
            #pragma unroll
            for (int c = 0; c < 4; c++) acc[a][b][c] = 0.0f;

    uint32_t aBase = (uint32_t)(((wm * 32 + (lane & 15)) * GLDA + (lane >> 4) * 8) * 2);
    uint32_t bBase = (uint32_t)(((wn * 64 + (lane & 7) + ((lane >> 4) & 1) * 8) * GLDA
                                 + ((lane >> 3) & 1) * 8) * 2);

    load_chunk(0, 0);
    for (int kc = 0; kc < GINC; kc++) {
        int s = kc & 1;
        if (kc + 1 < GINC) {
            load_chunk(kc + 1, s ^ 1);
            asm volatile("cp.async.wait_group 1;" ::: "memory");
        } else {
            asm volatile("cp.async.wait_group 0;" ::: "memory");
        }
        __syncthreads();
        uint32_t sa = sA + s * GBUF_B + aBase;
        uint32_t sbm = sB + s * GBUF_B + bBase;
        #pragma unroll
        for (int ks = 0; ks < 4; ks++) {
            uint32_t koff = (uint32_t)(ks * 16 * 2);
            uint32_t a0[4], a1[4];
            LDSM4(a0[0], a0[1], a0[2], a0[3], sa + koff);
            LDSM4(a1[0], a1[1], a1[2], a1[3], sa + 16 * GLDA * 2 + koff);
            uint32_t bf[16];
            #pragma unroll
            for (int nt = 0; nt < 4; nt++)
                LDSM4(bf[nt * 4 + 0], bf[nt * 4 + 1], bf[nt * 4 + 2], bf[nt * 4 + 3],
                      sbm + nt * 16 * GLDA * 2 + koff);
            #pragma unroll
            for (int j = 0; j < 8; j++) {
                int nt = j >> 1, hf = j & 1;
                MMA16816(acc[0][j], a0, bf[nt * 4 + hf * 2], bf[nt * 4 + hf * 2 + 1]);
                MMA16816(acc[1][j], a1, bf[nt * 4 + hf * 2], bf[nt * 4 + hf * 2 + 1]);
            }
        }
        __syncthreads();
    }

    // epilogue: scatter to [t][j][b] + bias
    #pragma unroll
    for (int mt = 0; mt < 2; mt++) {
        #pragma unroll
        for (int half = 0; half < 2; half++) {
            int m = m0 + wm * 32 + mt * 16 + (lane >> 2) + half * 8;
            int t = m >> 5, b = m & 31;
            float* obase = outg + (size_t)t * (H3 * BB) + b;
            #pragma unroll
            for (int j = 0; j < 8; j++) {
                int n = n0 + wn * 64 + j * 8 + (lane & 3) * 2;
                obase[(size_t)n * 32] = acc[mt][j][half * 2 + 0] + __ldg(bih + n);
                obase[(size_t)(n + 1) * 32] = acc[mt][j][half * 2 + 1] + __ldg(bih + n + 1);
            }
        }
    }
}

// ---------------- encoder scan ----------------
__global__ void __launch_bounds__(512) enc_scan(const float* __restrict__ Whh,
                                                const float* __restrict__ bhh) {
    int wid = threadIdx.x >> 5, lane = threadIdx.x & 31;
    int iLocal = wid & 3;
    int kq = wid >> 2;
    int i = blockIdx.x * 4 + iLocal;
    __shared__ float ps[4][3][3][32];

    for (int t = 0; t < SS; t++) {
        const float* hprev = t ? (g_eo + (t - 1) * (HH * BB)) : g_h0;
        float s0 = 0, s1 = 0, s2 = 0;
        {
            const float4* w0 = (const float4*)(Whh + (long)(i) * HH + kq * 128);
            const float4* w1 = (const float4*)(Whh + (long)(HH + i) * HH + kq * 128);
            const float4* w2 = (const float4*)(Whh + (long)(2 * HH + i) * HH + kq * 128);
            const float* hp = hprev + kq * 128 * 32 + lane;
            #pragma unroll 4
            for (int q = 0; q < 32; q++) {
                float h0 = hp[q * 128 + 0];
                float h1 = hp[q * 128 + 32];
                float h2 = hp[q * 128 + 64];
                float h3 = hp[q * 128 + 96];
                float4 w;
                w = w0[q]; s0 += w.x * h0 + w.y * h1 + w.z * h2 + w.w * h3;
                w = w1[q]; s1 += w.x * h0 + w.y * h1 + w.z * h2 + w.w * h3;
                w = w2[q]; s2 += w.x * h0 + w.y * h1 + w.z * h2 + w.w * h3;
            }
        }
        if (kq > 0) {
            ps[iLocal][kq - 1][0][lane] = s0;
            ps[iLocal][kq - 1][1][lane] = s1;
            ps[iLocal][kq - 1][2][lane] = s2;
        }
        __syncthreads();
        if (wid < 4) {
            float rh = s0 + ps[wid][0][0][lane] + ps[wid][1][0][lane] + ps[wid][2][0][lane] + bhh[i];
            float zh = s1 + ps[wid][0][1][lane] + ps[wid][1][1][lane] + ps[wid][2][1][lane] + bhh[HH + i];
            float nh = s2 + ps[wid][0][2][lane] + ps[wid][1][2][lane] + ps[wid][2][2][lane] + bhh[2 * HH + i];
            const float* gi = g_enc_gi + t * (H3 * BB);
            float ir = gi[i * 32 + lane];
            float iz = gi[(HH + i) * 32 + lane];
            float in_ = gi[(2 * HH + i) * 32 + lane];
            float r = sigm(ir + rh);
            float z = sigm(iz + zh);
            float n = tanhf(in_ + r * nh);
            float hv = hprev[i * 32 + lane];
            g_eo[t * (HH * BB) + i * 32 + lane] = (1.0f - z) * n + z * hv;
        }
        grid_sync(gridDim.x);
    }
}

__global__ void copyh() {
    int idx = blockIdx.x * 1024 + threadIdx.x;
    if (idx < HH * BB) g_hdec[0][idx] = g_eo[(SS - 1) * (HH * BB) + idx];
}

// ---------------- decoder scan ----------------
__global__ void __launch_bounds__(512) dec_scan(const float* __restrict__ Whh,
                                                const float* __restrict__ bhh,
                                                const float* __restrict__ Wih,
                                                const int* __restrict__ src) {
    int wid = threadIdx.x >> 5, lane = threadIdx.x & 31;
    __shared__ float psA[2][8][32];
    __shared__ float psC[4][4][32];
    __shared__ float denS[32];
    __shared__ float psD[4][3][6][32];

    for (int t = 0; t < TT; t++) {
        const float* h = g_hdec[t & 1];
        {
            int s = blockIdx.x * 2 + (wid & 1);
            int kq8 = wid >> 1;
            float acc = 0.0f;
            const float* eo = g_eo + s * (HH * BB) + kq8 * 64 * 32 + lane;
            const float* hp = h + kq8 * 64 * 32 + lane;
            #pragma unroll 8
            for (int k = 0; k < 64; k++) acc += eo[k * 32] * hp[k * 32];
            psA[wid & 1][kq8][lane] = acc;
            __syncthreads();
            if (wid < 2) {
                int ss2 = blockIdx.x * 2 + wid;
                float sc = 0.0f;
                #pragma unroll
                for (int q = 0; q < 8; q++) sc += psA[wid][q][lane];
                int tokv = src[lane * SS + ss2];
                float e = (tokv == 0) ? 0.0f : __expf(sc);
                g_scores[ss2 * 32 + lane] = e;
            }
        }
        grid_sync(gridDim.x);
        {
            int k = blockIdx.x * 4 + (wid & 3);
            int sq = wid >> 2;
            float acc = 0.0f;
            const float* eo = g_eo + sq * 64 * (HH * BB) + k * 32 + lane;
            const float* sce = g_scores + sq * 64 * 32 + lane;
            #pragma unroll 8
            for (int s = 0; s < 64; s++) acc += sce[s * 32] * eo[s * (HH * BB)];
            psC[wid & 3][sq][lane] = acc;
            if (wid == 0) {
                float d = 0.0f;
                const float* sp = g_scores + lane;
                #pragma unroll 8
                for (int s = 0; s < SS; s++) d += sp[s * 32];
                denS[lane] = d;
            }
            __syncthreads();
            if (wid < 4) {
                int kk = blockIdx.x * 4 + wid;
                float c = (psC[wid][0][lane] + psC[wid][1][lane] + psC[wid][2][lane] + psC[wid][3][lane])
                          / denS[lane];
                g_ctx[kk * 32 + lane] = c;
                g_pred[(t * 32 + lane) * (2 * HH) + HH + kk] = c;
            }
        }
        grid_sync(gridDim.x);
        {
            int i = blockIdx.x * 4 + (wid & 3);
            int kq = wid >> 2;
            float a0 = 0, a1 = 0, a2 = 0, c0 = 0, c1 = 0, c2 = 0;
            {
                const float4* wh0 = (const float4*)(Whh + (long)(i) * HH + kq * 128);
                const float4* wh1 = (const float4*)(Whh + (long)(HH + i) * HH + kq * 128);
                const float4* wh2 = (const float4*)(Whh + (long)(2 * HH + i) * HH + kq * 128);
                const float4* wc0 = (const float4*)(Wih + (long)(i) * 768 + EE + kq * 128);
                const float4* wc1 = (const float4*)(Wih + (long)(HH + i) * 768 + EE + kq * 128);
                const float4* wc2 = (const float4*)(Wih + (long)(2 * HH + i) * 768 + EE + kq * 128);
                const float* hp = h + kq * 128 * 32 + lane;
                const float* cp = g_ctx + kq * 128 * 32 + lane;
                #pragma unroll 4
                for (int q = 0; q < 32; q++) {
                    float h0 = hp[q * 128 + 0], h1 = hp[q * 128 + 32];
                    float h2 = hp[q * 128 + 64], h3 = hp[q * 128 + 96];
                    float x0 = cp[q * 128 + 0], x1 = cp[q * 128 + 32];
                    float x2 = cp[q * 128 + 64], x3 = cp[q * 128 + 96];
                    float4 w;
                    w = wh0[q]; a0 += w.x * h0 + w.y * h1 + w.z * h2 + w.w * h3;
                    w = wh1[q]; a1 += w.x * h0 + w.y * h1 + w.z * h2 + w.w * h3;
                    w = wh2[q]; a2 += w.x * h0 + w.y * h1 + w.z * h2 + w.w * h3;
                    w = wc0[q]; c0 += w.x * x0 + w.y * x1 + w.z * x2 + w.w * x3;
                    w = wc1[q]; c1 += w.x * x0 + w.y * x1 + w.z * x2 + w.w * x3;
                    w = wc2[q]; c2 += w.x * x0 + w.y * x1 + w.z * x2 + w.w * x3;
                }
            }
            if (kq > 0) {
                psD[wid & 3][kq - 1][0][lane] = a0;
                psD[wid & 3][kq - 1][1][lane] = a1;
                psD[wid & 3][kq - 1][2][lane] = a2;
                psD[wid & 3][kq - 1][3][lane] = c0;
                psD[wid & 3][kq - 1][4][lane] = c1;
                psD[wid & 3][kq - 1][5][lane] = c2;
            }
            __syncthreads();
            if (wid < 4) {
                float rh = a0, zh = a1, nh = a2, rc = c0, zc = c1, nc = c2;
                #pragma unroll
                for (int kk = 0; kk < 3; kk++) {
                    rh += psD[wid][kk][0][lane];
                    zh += psD[wid][kk][1][lane];
                    nh += psD[wid][kk][2][lane];
                    rc += psD[wid][kk][3][lane];
                    zc += psD[wid][kk][4][lane];
                    nc += psD[wid][kk][5][lane];
                }
                rh += bhh[i]; zh += bhh[HH + i]; nh += bhh[2 * HH + i];
                const float* gie = g_dec_gie + t * (H3 * BB);
                float ir = gie[i * 32 + lane] + rc;
                float iz = gie[(HH + i) * 32 + lane] + zc;
                float in_ = gie[(2 * HH + i) * 32 + lane] + nc;
                float r = sigm(ir + rh);
                float z = sigm(iz + zh);
                float n = tanhf(in_ + r * nh);
                float hold = h[i * 32 + lane];
                float hn = (1.0f - z) * n + z * hold;
                g_hdec[(t + 1) & 1][i * 32 + lane] = hn;
                g_pred[(t * 32 + lane) * (2 * HH) + i] = hn;
            }
        }
        grid_sync(gridDim.x);
    }
}

// ---------------- fc GEMM via mma.sync (HMMA bf16, K=3072) ----------------
__global__ void __launch_bounds__(256) fc_mma(const float* __restrict__ bias,
                                              float* __restrict__ out) {
    extern __shared__ uint8_t dynsmem[];
    uint32_t sA = smem_u32(dynsmem);
    uint32_t sB = sA + 2 * GBUF_B;

    int tid = threadIdx.x;
    int wid = tid >> 5, lane = tid & 31;
    int wm = wid & 3, wn = wid >> 2;
    int m0 = blockIdx.x * GBM;
    int n0 = blockIdx.y * GBN;

    const char* Ag = (const char*)(g_Ab + (size_t)m0 * KTOT);
    const char* Bg = (const char*)(g_Wb + (size_t)n0 * KTOT);

    int lrow = tid >> 3, lu = tid & 7;
    auto load_chunk = [&](int kc, int s) {
        uint32_t sa = sA + s * GBUF_B;
        uint32_t sbm = sB + s * GBUF_B;
        size_t gk = (size_t)kc * GBK * 2;
        #pragma unroll
        for (int it = 0; it < 4; it++) {
            int row = it * 32 + lrow;
            uint32_t doff = (uint32_t)(row * (GLDA * 2) + lu * 16);
            cpasync16(sa + doff, Ag + (size_t)row * (KTOT * 2) + gk + lu * 16);
            cpasync16(sbm + doff, Bg + (size_t)row * (KTOT * 2) + gk + lu * 16);
        }
        asm volatile("cp.async.commit_group;" ::: "memory");
    };

    float acc[2][8][4];
    #pragma unroll
    for (int a = 0; a < 2; a++)
        #pragma unroll
        for (int b = 0; b < 8; b++)
            #pragma unroll
            for (int c = 0; c < 4; c++) acc[a][b][c] = 0.0f;

    uint32_t aBase = (uint32_t)(((wm * 32 + (lane & 15)) * GLDA + (lane >> 4) * 8) * 2);
    uint32_t bBase = (uint32_t)(((wn * 64 + (lane & 7) + ((lane >> 4) & 1) * 8) * GLDA
                                 + ((lane >> 3) & 1) * 8) * 2);

    load_chunk(0, 0);
    for (int kc = 0; kc < GNC; kc++) {
        int s = kc & 1;
        if (kc + 1 < GNC) {
            load_chunk(kc + 1, s ^ 1);
            asm volatile("cp.async.wait_group 1;" ::: "memory");
        } else {
            asm volatile("cp.async.wait_group 0;" ::: "memory");
        }
        __syncthreads();
        uint32_t sa = sA + s * GBUF_B + aBase;
        uint32_t sbm = sB + s * GBUF_B + bBase;
        #pragma unroll
        for (int ks = 0; ks < 4; ks++) {
            uint32_t koff = (uint32_t)(ks * 16 * 2);
            uint32_t a0[4], a1[4];
            LDSM4(a0[0], a0[1], a0[2], a0[3], sa + koff);
            LDSM4(a1[0], a1[1], a1[2], a1[3], sa + 16 * GLDA * 2 + koff);
            uint32_t bf[16];
            #pragma unroll
            for (int nt = 0; nt < 4; nt++)
                LDSM4(bf[nt * 4 + 0], bf[nt * 4 + 1], bf[nt * 4 + 2], bf[nt * 4 + 3],
                      sbm + nt * 16 * GLDA * 2 + koff);
            #pragma unroll
            for (int j = 0; j < 8; j++) {
                int nt = j >> 1, hf = j & 1;
                MMA16816(acc[0][j], a0, bf[nt * 4 + hf * 2], bf[nt * 4 + hf * 2 + 1]);
                MMA16816(acc[1][j], a1, bf[nt * 4 + hf * 2], bf[nt * 4 + hf * 2 + 1]);
            }
        }
        __syncthreads();
    }

    float bv[8][2];
    #pragma unroll
    for (int j = 0; j < 8; j++) {
        int n = n0 + wn * 64 + j * 8 + (lane & 3) * 2;
        bv[j][0] = __ldg(bias + n);
        bv[j][1] = __ldg(bias + n + 1);
    }
    #pragma unroll
    for (int mt = 0; mt < 2; mt++) {
        #pragma unroll
        for (int half = 0; half < 2; half++) {
            int m = m0 + wm * 32 + mt * 16 + (lane >> 2) + half * 8;
            int t = m >> 5, b = m & 31;
            float* orow = out + (size_t)b * (TT * VV) + (size_t)t * VV;
            #pragma unroll
            for (int j = 0; j < 8; j++) {
                int n = n0 + wn * 64 + j * 8 + (lane & 3) * 2;
                float2 v;
                v.x = acc[mt][j][half * 2 + 0] + bv[j][0];
                v.y = acc[mt][j][half * 2 + 1] + bv[j][1];
                *(float2*)(orow + n) = v;
            }
        }
    }
}

// ---------------- launch ----------------
extern "C" void kernel_launch(void* const* d_in, const int* in_sizes, int n_in,
                              void* d_out, int out_size) {
    const int* src = (const int*)d_in[0];
    const int* tgt = (const int*)d_in[2];
    const float* enc_emb = (const float*)d_in[3];
    const float* enc_Wih = (const float*)d_in[4];
    const float* enc_Whh = (const float*)d_in[5];
    const float* enc_bih = (const float*)d_in[6];
    const float* enc_bhh = (const float*)d_in[7];
    const float* dec_emb = (const float*)d_in[8];
    const float* dec_Wih = (const float*)d_in[9];
    const float* dec_Whh = (const float*)d_in[10];
    const float* dec_bih = (const float*)d_in[11];
    const float* dec_bhh = (const float*)d_in[12];
    const float* fc_W = (const float*)d_in[13];
    const float* fc_b = (const float*)d_in[14];
    float* out = (float*)d_out;

    cudaFuncSetAttribute(fc_mma, cudaFuncAttributeMaxDynamicSharedMemorySize, FC_SMEM);
    cudaFuncSetAttribute(gi_mma, cudaFuncAttributeMaxDynamicSharedMemorySize, FC_SMEM);

    init_k<<<16, 1024>>>();
    convW<<<(VV * 1024) / 4096, 1024>>>(fc_W);
    gatherX<<<SS * BB / 8, 256>>>(enc_emb, src, SS, 0);
    gatherX<<<TT * BB / 8, 256>>>(dec_emb, tgt, TT, 1);
    splitWih<<<H3 / 8, 256>>>(enc_Wih, EE, 0);
    splitWih<<<H3 / 8, 256>>>(dec_Wih, EE + HH, 1);
    gi_mma<<<dim3(SS * BB / GBM, H3 / GBN), 256, FC_SMEM>>>(enc_bih, 0);
    gi_mma<<<dim3(TT * BB / GBM, H3 / GBN), 256, FC_SMEM>>>(dec_bih, 1);
    enc_scan<<<128, 512>>>(enc_Whh, enc_bhh);
    copyh<<<16, 1024>>>();
    dec_scan<<<128, 512>>>(dec_Whh, dec_bhh, dec_Wih, src);
    convA<<<512, 1024>>>();
    fc_mma<<<dim3(TT * BB / GBM, VV / GBN), 256, FC_SMEM>>>(fc_b, out);
}